// round 16
// baseline (speedup 1.0000x reference)
#include <cuda_runtime.h>
#include <cuda_fp16.h>
#include <math.h>
#include <stdint.h>

// ContrastiveLoss: loss = sum_i [ logsumexp_j(X_i.Y_j/T) - X_i.Y_i/T ]
// N=8192, C=512, T=0.07. fp16 mma.sync m16n8k16 (fp32 accum), fragment-major
// prepacked operands, 4-warp CTAs / 64x64 warp tiles / occ 2, persistent
// grid=296 static schedule, race-free 3-stage cp.async ring, full B-fragment
// hoist at step start (max LDS/HMMA overlap), fused LSE + 1-pass reduce.

#define NTOT 8192
#define CDIM 512
#define NCTA 296
#define NUNITS 4096                   // 64 rowblks x 64 coltiles (128x128 tiles)
#define NCOLT 64
#define NPART (NCOLT * 2)

#define STEPS_PER_UNIT 8              // step = 64-wide k chunk
#define XSTAGE_BYTES 16384
#define STAGE_BYTES  32768
#define NSTAGE 3
#define SMEM_TOTAL (NSTAGE * STAGE_BYTES)   // 98304 -> occ 2

#define PLANE_HALFS 524288

#define SCALE_LOG2 (14.285714285714286f * 1.4426950408889634f)
#define LN2 0.6931471805599453f

// -------- scratch (device globals; no allocation allowed) --------
__device__ __align__(16) __half g_Xh[NTOT * CDIM];
__device__ __align__(16) __half g_Yh[NTOT * CDIM];
__device__ float g_m[NPART][NTOT];
__device__ float g_l[NPART][NTOT];
__device__ float g_pos[NTOT];
__device__ float g_bsum[64];
__device__ unsigned int g_done;

__device__ __forceinline__ float ex2f(float x) {
    float y; asm("ex2.approx.ftz.f32 %0, %1;" : "=f"(y) : "f"(x)); return y;
}
__device__ __forceinline__ uint32_t smem_to_u32(const void* p) {
    uint32_t a;
    asm("{ .reg .u64 t; cvta.to.shared.u64 t, %1; cvt.u32.u64 %0, t; }" : "=r"(a) : "l"(p));
    return a;
}
__device__ __forceinline__ void cp_async16(uint32_t dst, const void* src) {
    asm volatile("cp.async.ca.shared.global [%0], [%1], 16;" :: "r"(dst), "l"(src) : "memory");
}
#define CP_COMMIT() asm volatile("cp.async.commit_group;" ::: "memory")
#define CP_WAIT_1() asm volatile("cp.async.wait_group 1;" ::: "memory")

__device__ __forceinline__ uint32_t pk(float a, float b) {
    __half2 h = __floats2half2_rn(a, b);
    return *reinterpret_cast<uint32_t*>(&h);
}
__device__ __forceinline__ void mma_f16(float* c, const uint4 a, uint32_t b0, uint32_t b1) {
    asm volatile(
        "mma.sync.aligned.m16n8k16.row.col.f32.f16.f16.f32 "
        "{%0,%1,%2,%3}, {%4,%5,%6,%7}, {%8,%9}, {%0,%1,%2,%3};"
        : "+f"(c[0]), "+f"(c[1]), "+f"(c[2]), "+f"(c[3])
        : "r"(a.x), "r"(a.y), "r"(a.z), "r"(a.w), "r"(b0), "r"(b1));
}

// -------- pre-kernel: fp16 round + fragment-major packing --------
__global__ void __launch_bounds__(256)
cl_pre_kernel(const float* __restrict__ X, const float* __restrict__ Y) {
    const uint32_t gid = blockIdx.x * 256u + threadIdx.x;
    const uint32_t NFRAG = 524288;
    if (gid < NFRAG) {
        const uint32_t fid = gid;
        const uint32_t lane = fid & 31, k16 = (fid >> 5) & 3, rb = (fid >> 7) & 511, kc = fid >> 16;
        const uint32_t g = lane >> 2, q = lane & 3;
        const uint32_t k0 = kc * 64 + k16 * 16;
        const float* r0 = X + (size_t)(rb * 16 + g) * CDIM + k0;
        const float* r1 = r0 + 8 * CDIM;
        uint4 o;
        o.x = pk(r0[2 * q], r0[2 * q + 1]);
        o.y = pk(r1[2 * q], r1[2 * q + 1]);
        o.z = pk(r0[2 * q + 8], r0[2 * q + 9]);
        o.w = pk(r1[2 * q + 8], r1[2 * q + 9]);
        *reinterpret_cast<uint4*>(reinterpret_cast<char*>(g_Xh) + (size_t)fid * 16) = o;
    } else {
        const uint32_t fid = gid - NFRAG;
        const uint32_t lane = fid & 31, kp = (fid >> 5) & 1, cb = (fid >> 6) & 1023, kc = fid >> 16;
        const uint32_t g = lane >> 2, q = lane & 3;
        const uint32_t k0 = kc * 64 + kp * 32;
        const float* r = Y + (size_t)(cb * 8 + g) * CDIM + k0;
        uint4 o;
        o.x = pk(r[2 * q], r[2 * q + 1]);
        o.y = pk(r[2 * q + 8], r[2 * q + 9]);
        o.z = pk(r[16 + 2 * q], r[16 + 2 * q + 1]);
        o.w = pk(r[16 + 2 * q + 8], r[16 + 2 * q + 9]);
        *reinterpret_cast<uint4*>(reinterpret_cast<char*>(g_Yh) + (size_t)fid * 16) = o;
    }
}

// -------- main kernel: persistent, 4 warps, 64x64 warp tiles, fp16 --------
__global__ void __launch_bounds__(128, 2)
cl_mma_kernel() {
    extern __shared__ __align__(16) char smem[];
    const uint32_t sb = smem_to_u32(smem);
    const uint4* sm4 = reinterpret_cast<const uint4*>(smem);

    const int tid = threadIdx.x;
    const int wid = tid >> 5;
    const int lane = tid & 31;
    const int g = lane >> 2;
    const int q = lane & 3;
    const int warpM = wid >> 1;
    const int warpN = wid & 1;

    const int b = blockIdx.x;
    const int njobs = (NUNITS - 1 - b) / NCTA + 1;   // 13 or 14
    const int nsteps = njobs * STEPS_PER_UNIT;

    auto load_stage = [&](int s, int buf) {
        if (s < nsteps) {
            const int j = s >> 3;
            const int kc = s & 7;
            const int uid = b + NCTA * j;
            const int row0 = (uid >> 6) * 128;
            const int col0 = (uid & 63) * 128;
            const __half* xsrc = g_Xh + (size_t)kc * PLANE_HALFS + (size_t)(row0 >> 4) * 1024;
            const __half* ysrc = g_Yh + (size_t)kc * PLANE_HALFS + (size_t)(col0 >> 3) * 512;
            const uint32_t xd = sb + buf * STAGE_BYTES;
            const uint32_t yd = xd + XSTAGE_BYTES;
#pragma unroll
            for (int i = 0; i < 8; i++) {
                const int c = tid + i * 128;
                cp_async16(xd + c * 16, xsrc + c * 8);
                cp_async16(yd + c * 16, ysrc + c * 8);
            }
        }
        CP_COMMIT();
    };

    float acc[4][8][4];
#pragma unroll
    for (int mb = 0; mb < 4; mb++)
#pragma unroll
        for (int nb = 0; nb < 8; nb++)
#pragma unroll
            for (int c = 0; c < 4; c++) acc[mb][nb][c] = 0.0f;

    load_stage(0, 0);
    load_stage(1, 1);

    for (int s = 0; s < nsteps; s++) {
        const int buf = s % NSTAGE;

        // RACE-FREE ordering: own-wait -> barrier -> read (see R14 notes).
        CP_WAIT_1();
        __syncthreads();

        const uint4* Xf = sm4 + (buf * STAGE_BYTES) / 16;   // [rb(8)][k16(4)][lane]
        const uint4* Yf = Xf + XSTAGE_BYTES / 16;           // [cb(16)][kpair(2)][lane]

        // ---- hoist ALL B fragments (both kp halves) before any MMA ----
        uint4 bq[2][8];
#pragma unroll
        for (int kp = 0; kp < 2; kp++)
#pragma unroll
            for (int nb = 0; nb < 8; nb++)
                bq[kp][nb] = Yf[((warpN * 8 + nb) * 2 + kp) * 32 + lane];

#pragma unroll
        for (int kp = 0; kp < 2; kp++) {
#pragma unroll
            for (int half = 0; half < 2; half++) {
                const int k16 = kp * 2 + half;
#pragma unroll
                for (int mb = 0; mb < 4; mb++) {
                    const uint4 av = Xf[((warpM * 4 + mb) * 4 + k16) * 32 + lane];
#pragma unroll
                    for (int nb = 0; nb < 8; nb++) {
                        if (half == 0) mma_f16(acc[mb][nb], av, bq[kp][nb].x, bq[kp][nb].y);
                        else           mma_f16(acc[mb][nb], av, bq[kp][nb].z, bq[kp][nb].w);
                    }
                }
            }
            // mid-compute prefetch issue: LSU burst overlaps second compute half
            if (kp == 0) load_stage(s + 2, (s + 2) % NSTAGE);
        }

        // per-unit epilogue: stripe-local (max, sum) partials, then reset acc
        if ((s & 7) == 7) {
            const int uid = b + NCTA * (s >> 3);
            const int row0 = (uid >> 6) * 128;
            const int ct = uid & 63;
            const int sp = ct * 2 + warpN;
            const int col0 = ct * 128 + warpN * 64;
#pragma unroll
            for (int mb = 0; mb < 4; mb++) {
#pragma unroll
                for (int pr = 0; pr < 2; pr++) {
                    const int grow = row0 + warpM * 64 + mb * 16 + pr * 8 + g;
                    float v[16];
                    float tmax = -INFINITY;
#pragma unroll
                    for (int nb = 0; nb < 8; nb++) {
                        v[2 * nb] = acc[mb][nb][2 * pr] * SCALE_LOG2;
                        v[2 * nb + 1] = acc[mb][nb][2 * pr + 1] * SCALE_LOG2;
                        tmax = fmaxf(tmax, fmaxf(v[2 * nb], v[2 * nb + 1]));
                    }
                    tmax = fmaxf(tmax, __shfl_xor_sync(0xffffffffu, tmax, 1));
                    tmax = fmaxf(tmax, __shfl_xor_sync(0xffffffffu, tmax, 2));
                    float sum = 0.0f;
#pragma unroll
                    for (int nb = 0; nb < 8; nb++) {
                        const int gc = col0 + nb * 8 + q * 2;
                        sum += ex2f(v[2 * nb] - tmax) + ex2f(v[2 * nb + 1] - tmax);
                        if (gc == grow) g_pos[grow] = v[2 * nb];
                        if (gc + 1 == grow) g_pos[grow] = v[2 * nb + 1];
                    }
                    sum += __shfl_xor_sync(0xffffffffu, sum, 1);
                    sum += __shfl_xor_sync(0xffffffffu, sum, 2);
                    if (q == 0) {
                        g_m[sp][grow] = tmax;
                        g_l[sp][grow] = sum;
                    }
                }
            }
#pragma unroll
            for (int mb = 0; mb < 4; mb++)
#pragma unroll
                for (int nb = 0; nb < 8; nb++)
#pragma unroll
                    for (int c = 0; c < 4; c++) acc[mb][nb][c] = 0.0f;
        }
    }
}

// -------- fused combine + reduce (grid 64 x 128; last block finishes) --------
__global__ void cl_combine_kernel(float* __restrict__ out) {
    __shared__ float sh[128];
    const int i = blockIdx.x * 128 + threadIdx.x;
    float M = -INFINITY;
#pragma unroll 8
    for (int s = 0; s < NPART; s++) M = fmaxf(M, g_m[s][i]);
    float L = 0.0f;
#pragma unroll 8
    for (int s = 0; s < NPART; s++) L += g_l[s][i] * ex2f(g_m[s][i] - M);
    sh[threadIdx.x] = M + __log2f(L) - g_pos[i];
    __syncthreads();
    for (int o = 64; o > 0; o >>= 1) {
        if (threadIdx.x < o) sh[threadIdx.x] += sh[threadIdx.x + o];
        __syncthreads();
    }
    if (threadIdx.x == 0) {
        g_bsum[blockIdx.x] = sh[0];
        __threadfence();
        const unsigned int t = atomicAdd(&g_done, 1u);
        if (t == 63u) {
            float tot = 0.0f;
#pragma unroll
            for (int k = 0; k < 64; k++) tot += g_bsum[k];
            out[0] = tot * LN2;
            g_done = 0u;   // reset for graph replay
        }
    }
}

extern "C" void kernel_launch(void* const* d_in, const int* in_sizes, int n_in,
                              void* d_out, int out_size) {
    const float* X = (const float*)d_in[0];
    const float* Y = (const float*)d_in[1];
    float* out = (float*)d_out;

    cudaFuncSetAttribute(cl_mma_kernel, cudaFuncAttributeMaxDynamicSharedMemorySize, SMEM_TOTAL);

    cl_pre_kernel<<<4096, 256>>>(X, Y);
    cl_mma_kernel<<<NCTA, 128, SMEM_TOTAL>>>();
    cl_combine_kernel<<<64, 128>>>(out);
}

// round 17
// speedup vs baseline: 1.0425x; 1.0425x over previous
#include <cuda_runtime.h>
#include <cuda_fp16.h>
#include <math.h>
#include <stdint.h>

// ContrastiveLoss: loss = sum_i [ logsumexp_j(X_i.Y_j/T) - X_i.Y_i/T ]
// N=8192, C=512, T=0.07. fp16 mma.sync m16n8k16 (fp32 accum), fragment-major
// prepacked operands via smem-staged coalesced pre-kernel, 4-warp CTAs /
// 64x64 warp tiles / occ 2, persistent grid=296, race-free 3-stage cp.async
// ring (R14 mainloop, untouched), fused LSE partials + 1-pass reduce.

#define NTOT 8192
#define CDIM 512
#define NCTA 296
#define NUNITS 4096                   // 64 rowblks x 64 coltiles (128x128 tiles)
#define NCOLT 64
#define NPART (NCOLT * 2)

#define STEPS_PER_UNIT 8              // step = 64-wide k chunk
#define XSTAGE_BYTES 16384
#define STAGE_BYTES  32768
#define NSTAGE 3
#define SMEM_TOTAL (NSTAGE * STAGE_BYTES)   // 98304 -> occ 2

#define PLANE_HALFS 524288

#define SCALE_LOG2 (14.285714285714286f * 1.4426950408889634f)
#define LN2 0.6931471805599453f

// -------- scratch (device globals; no allocation allowed) --------
__device__ __align__(16) __half g_Xh[NTOT * CDIM];
__device__ __align__(16) __half g_Yh[NTOT * CDIM];
__device__ float g_m[NPART][NTOT];
__device__ float g_l[NPART][NTOT];
__device__ float g_pos[NTOT];
__device__ float g_bsum[64];
__device__ unsigned int g_done;

__device__ __forceinline__ float ex2f(float x) {
    float y; asm("ex2.approx.ftz.f32 %0, %1;" : "=f"(y) : "f"(x)); return y;
}
__device__ __forceinline__ uint32_t smem_to_u32(const void* p) {
    uint32_t a;
    asm("{ .reg .u64 t; cvta.to.shared.u64 t, %1; cvt.u32.u64 %0, t; }" : "=r"(a) : "l"(p));
    return a;
}
__device__ __forceinline__ void cp_async16(uint32_t dst, const void* src) {
    asm volatile("cp.async.ca.shared.global [%0], [%1], 16;" :: "r"(dst), "l"(src) : "memory");
}
#define CP_COMMIT() asm volatile("cp.async.commit_group;" ::: "memory")
#define CP_WAIT_1() asm volatile("cp.async.wait_group 1;" ::: "memory")

__device__ __forceinline__ uint32_t pk(float a, float b) {
    __half2 h = __floats2half2_rn(a, b);
    return *reinterpret_cast<uint32_t*>(&h);
}
__device__ __forceinline__ void mma_f16(float* c, const uint4 a, uint32_t b0, uint32_t b1) {
    asm volatile(
        "mma.sync.aligned.m16n8k16.row.col.f32.f16.f16.f32 "
        "{%0,%1,%2,%3}, {%4,%5,%6,%7}, {%8,%9}, {%0,%1,%2,%3};"
        : "+f"(c[0]), "+f"(c[1]), "+f"(c[2]), "+f"(c[3])
        : "r"(a.x), "r"(a.y), "r"(a.z), "r"(a.w), "r"(b0), "r"(b1));
}

// -------- pre-kernel: coalesced read -> smem transpose -> coalesced write --
// X blocks (b < 4096): tile (rb = b&511, kc = b>>9): rows rb*16..+15, cols kc*64..+63.
//   smem word [r][j] (stride 36) = half2 of cols (2j, 2j+1) of row r.
//   A fragment (k16, lane(g,q)): {[g][k16*8+q], [g+8][k16*8+q], [g][+4], [g+8][+4]}
//   bank(4g+q+c) = lane+c -> conflict-free.
// Y blocks (b >= 4096): two tiles each (cb = ty&1023, kc = ty>>10): 8 rows x 64 cols.
//   B fragment (kp, lane(g,q)): {[g][kp*16+q], [g][+4], [g][+8], [g][+12]}
__global__ void __launch_bounds__(256)
cl_pre_kernel(const float* __restrict__ X, const float* __restrict__ Y) {
    __shared__ uint32_t sx[16][36];    // X tile: 16 rows x 32 half2-words (+pad)
    const int tid = threadIdx.x;
    const int b = blockIdx.x;

    if (b < 4096) {
        const int rb = b & 511, kc = b >> 9;
        // coalesced read: 1024 floats, thread -> one float4
        const int row = tid >> 4;
        const int c4 = tid & 15;
        float4 v = *reinterpret_cast<const float4*>(
            X + (size_t)(rb * 16 + row) * CDIM + kc * 64 + c4 * 4);
        sx[row][c4 * 2] = pk(v.x, v.y);
        sx[row][c4 * 2 + 1] = pk(v.z, v.w);
        __syncthreads();
        if (tid < 128) {
            const int k16 = tid >> 5, lane = tid & 31;
            const int g = lane >> 2, q = lane & 3;
            uint4 o;
            o.x = sx[g][k16 * 8 + q];
            o.y = sx[g + 8][k16 * 8 + q];
            o.z = sx[g][k16 * 8 + q + 4];
            o.w = sx[g + 8][k16 * 8 + q + 4];
            const uint32_t fid = ((uint32_t)kc << 16) | ((uint32_t)rb << 7) | ((uint32_t)tid & 127);
            *reinterpret_cast<uint4*>(reinterpret_cast<char*>(g_Xh) + (size_t)fid * 16) = o;
        }
    } else {
        __shared__ uint32_t sy[2][8][36];   // two Y tiles: 8 rows x 32 words (+pad)
        const int t2 = b - 4096;
        // coalesced read: 2 tiles x 512 floats; thread -> one float4
        const int t = tid >> 7;
        const int i = tid & 127;
        const int row = i >> 4;
        const int c4 = i & 15;
        const int ty = t2 * 2 + t;
        const int cb = ty & 1023, kc = ty >> 10;
        float4 v = *reinterpret_cast<const float4*>(
            Y + (size_t)(cb * 8 + row) * CDIM + kc * 64 + c4 * 4);
        sy[t][row][c4 * 2] = pk(v.x, v.y);
        sy[t][row][c4 * 2 + 1] = pk(v.z, v.w);
        __syncthreads();
        if (tid < 128) {
            const int tw = tid >> 6;          // which tile
            const int j = tid & 63;           // fragment within tile
            const int kp = j >> 5, lane = j & 31;
            const int g = lane >> 2, q = lane & 3;
            const int tyw = t2 * 2 + tw;
            const int cbw = tyw & 1023, kcw = tyw >> 10;
            uint4 o;
            o.x = sy[tw][g][kp * 16 + q];
            o.y = sy[tw][g][kp * 16 + q + 4];
            o.z = sy[tw][g][kp * 16 + q + 8];
            o.w = sy[tw][g][kp * 16 + q + 12];
            const uint32_t fid = ((uint32_t)kcw << 16) | ((uint32_t)cbw << 6) | (uint32_t)j;
            *reinterpret_cast<uint4*>(reinterpret_cast<char*>(g_Yh) + (size_t)fid * 16) = o;
        }
    }
}

// -------- main kernel: persistent, 4 warps, 64x64 warp tiles, fp16 (R14) ----
__global__ void __launch_bounds__(128, 2)
cl_mma_kernel() {
    extern __shared__ __align__(16) char smem[];
    const uint32_t sb = smem_to_u32(smem);
    const uint4* sm4 = reinterpret_cast<const uint4*>(smem);

    const int tid = threadIdx.x;
    const int wid = tid >> 5;
    const int lane = tid & 31;
    const int g = lane >> 2;
    const int q = lane & 3;
    const int warpM = wid >> 1;
    const int warpN = wid & 1;

    const int b = blockIdx.x;
    const int njobs = (NUNITS - 1 - b) / NCTA + 1;   // 13 or 14
    const int nsteps = njobs * STEPS_PER_UNIT;

    auto load_stage = [&](int s, int buf) {
        if (s < nsteps) {
            const int j = s >> 3;
            const int kc = s & 7;
            const int uid = b + NCTA * j;
            const int row0 = (uid >> 6) * 128;
            const int col0 = (uid & 63) * 128;
            const __half* xsrc = g_Xh + (size_t)kc * PLANE_HALFS + (size_t)(row0 >> 4) * 1024;
            const __half* ysrc = g_Yh + (size_t)kc * PLANE_HALFS + (size_t)(col0 >> 3) * 512;
            const uint32_t xd = sb + buf * STAGE_BYTES;
            const uint32_t yd = xd + XSTAGE_BYTES;
#pragma unroll
            for (int i = 0; i < 8; i++) {
                const int c = tid + i * 128;
                cp_async16(xd + c * 16, xsrc + c * 8);
                cp_async16(yd + c * 16, ysrc + c * 8);
            }
        }
        CP_COMMIT();
    };

    float acc[4][8][4];
#pragma unroll
    for (int mb = 0; mb < 4; mb++)
#pragma unroll
        for (int nb = 0; nb < 8; nb++)
#pragma unroll
            for (int c = 0; c < 4; c++) acc[mb][nb][c] = 0.0f;

    load_stage(0, 0);
    load_stage(1, 1);

    for (int s = 0; s < nsteps; s++) {
        const int buf = s % NSTAGE;

        // RACE-FREE ordering: own-wait -> barrier -> read (see R14 notes).
        CP_WAIT_1();
        __syncthreads();

        const uint4* Xf = sm4 + (buf * STAGE_BYTES) / 16;   // [rb(8)][k16(4)][lane]
        const uint4* Yf = Xf + XSTAGE_BYTES / 16;           // [cb(16)][kpair(2)][lane]

#pragma unroll
        for (int kp = 0; kp < 2; kp++) {
            uint4 bq[8];
#pragma unroll
            for (int nb = 0; nb < 8; nb++)
                bq[nb] = Yf[((warpN * 8 + nb) * 2 + kp) * 32 + lane];
#pragma unroll
            for (int half = 0; half < 2; half++) {
                const int k16 = kp * 2 + half;
#pragma unroll
                for (int mb = 0; mb < 4; mb++) {
                    const uint4 av = Xf[((warpM * 4 + mb) * 4 + k16) * 32 + lane];
#pragma unroll
                    for (int nb = 0; nb < 8; nb++) {
                        if (half == 0) mma_f16(acc[mb][nb], av, bq[nb].x, bq[nb].y);
                        else           mma_f16(acc[mb][nb], av, bq[nb].z, bq[nb].w);
                    }
                }
            }
            // mid-compute prefetch issue: LSU burst overlaps second compute half
            if (kp == 0) load_stage(s + 2, (s + 2) % NSTAGE);
        }

        // per-unit epilogue: stripe-local (max, sum) partials, then reset acc
        if ((s & 7) == 7) {
            const int uid = b + NCTA * (s >> 3);
            const int row0 = (uid >> 6) * 128;
            const int ct = uid & 63;
            const int sp = ct * 2 + warpN;
            const int col0 = ct * 128 + warpN * 64;
#pragma unroll
            for (int mb = 0; mb < 4; mb++) {
#pragma unroll
                for (int pr = 0; pr < 2; pr++) {
                    const int grow = row0 + warpM * 64 + mb * 16 + pr * 8 + g;
                    float v[16];
                    float tmax = -INFINITY;
#pragma unroll
                    for (int nb = 0; nb < 8; nb++) {
                        v[2 * nb] = acc[mb][nb][2 * pr] * SCALE_LOG2;
                        v[2 * nb + 1] = acc[mb][nb][2 * pr + 1] * SCALE_LOG2;
                        tmax = fmaxf(tmax, fmaxf(v[2 * nb], v[2 * nb + 1]));
                    }
                    tmax = fmaxf(tmax, __shfl_xor_sync(0xffffffffu, tmax, 1));
                    tmax = fmaxf(tmax, __shfl_xor_sync(0xffffffffu, tmax, 2));
                    float sum = 0.0f;
#pragma unroll
                    for (int nb = 0; nb < 8; nb++) {
                        const int gc = col0 + nb * 8 + q * 2;
                        sum += ex2f(v[2 * nb] - tmax) + ex2f(v[2 * nb + 1] - tmax);
                        if (gc == grow) g_pos[grow] = v[2 * nb];
                        if (gc + 1 == grow) g_pos[grow] = v[2 * nb + 1];
                    }
                    sum += __shfl_xor_sync(0xffffffffu, sum, 1);
                    sum += __shfl_xor_sync(0xffffffffu, sum, 2);
                    if (q == 0) {
                        g_m[sp][grow] = tmax;
                        g_l[sp][grow] = sum;
                    }
                }
            }
#pragma unroll
            for (int mb = 0; mb < 4; mb++)
#pragma unroll
                for (int nb = 0; nb < 8; nb++)
#pragma unroll
                    for (int c = 0; c < 4; c++) acc[mb][nb][c] = 0.0f;
        }
    }
}

// -------- fused combine + reduce (grid 64 x 128; last block finishes) --------
__global__ void cl_combine_kernel(float* __restrict__ out) {
    __shared__ float sh[128];
    const int i = blockIdx.x * 128 + threadIdx.x;
    float M = -INFINITY;
#pragma unroll 8
    for (int s = 0; s < NPART; s++) M = fmaxf(M, g_m[s][i]);
    float L = 0.0f;
#pragma unroll 8
    for (int s = 0; s < NPART; s++) L += g_l[s][i] * ex2f(g_m[s][i] - M);
    sh[threadIdx.x] = M + __log2f(L) - g_pos[i];
    __syncthreads();
    for (int o = 64; o > 0; o >>= 1) {
        if (threadIdx.x < o) sh[threadIdx.x] += sh[threadIdx.x + o];
        __syncthreads();
    }
    if (threadIdx.x == 0) {
        g_bsum[blockIdx.x] = sh[0];
        __threadfence();
        const unsigned int t = atomicAdd(&g_done, 1u);
        if (t == 63u) {
            float tot = 0.0f;
#pragma unroll
            for (int k = 0; k < 64; k++) tot += g_bsum[k];
            out[0] = tot * LN2;
            g_done = 0u;   // reset for graph replay
        }
    }
}

extern "C" void kernel_launch(void* const* d_in, const int* in_sizes, int n_in,
                              void* d_out, int out_size) {
    const float* X = (const float*)d_in[0];
    const float* Y = (const float*)d_in[1];
    float* out = (float*)d_out;

    cudaFuncSetAttribute(cl_mma_kernel, cudaFuncAttributeMaxDynamicSharedMemorySize, SMEM_TOTAL);

    cl_pre_kernel<<<8192, 256>>>(X, Y);
    cl_mma_kernel<<<NCTA, 128, SMEM_TOTAL>>>();
    cl_combine_kernel<<<64, 128>>>(out);
}